// round 9
// baseline (speedup 1.0000x reference)
#include <cuda_runtime.h>
#include <math.h>

#define NMAX 8
#define LMMAX 16
#define N_SPECIES 4
#define NSEG 80000
#define CAP 32
#define OVF_CAP 4096

static constexpr float RC = 5.0f;
static constexpr float SMOOTH_W = 0.5f;
static constexpr float PI_F = 3.14159265358979323846f;
static constexpr float S_EXP = 1.69864363f;   // sqrt(2*log2(e))

// 32-byte bucket entry: data + log2(cutoff) in one L2 sector.
struct __align__(32) Entry {
    float4 v;        // (S_EXP*r, x, y, z)
    float  lfc;      // log2(fc); -inf when fc == 0
    float  pad0, pad1, pad2;
};

// Static scratch. d_cnt[NSEG] doubles as overflow counter.
__device__ int   d_cnt[NSEG + 1];
__device__ Entry d_bucket[NSEG * CAP];     // 82 MB region, ~26 MB touched
__device__ Entry d_ovf[OVF_CAP];
__device__ int   d_ovf_seg[OVF_CAP];

__device__ __forceinline__ float ex2(float a) {
    float y;
    asm("ex2.approx.ftz.f32 %0, %1;" : "=f"(y) : "f"(a));
    return y;
}

__device__ __forceinline__ float cutoff_branchless(float r) {
    float t = __saturatef((r - (RC - SMOOTH_W)) * (1.0f / SMOOTH_W));
    return 0.5f * (1.0f + __cosf(PI_F * t));
}

__device__ __forceinline__ void sph_harm(float x, float y, float zd, float* Y) {
    float x2 = x * x, y2 = y * y, z2 = zd * zd;
    Y[0]  = 0.28209479177387814f;
    Y[1]  = 0.4886025119029199f * y;
    Y[2]  = 0.4886025119029199f * zd;
    Y[3]  = 0.4886025119029199f * x;
    Y[4]  = 1.0925484305920792f * x * y;
    Y[5]  = 1.0925484305920792f * y * zd;
    Y[6]  = 0.31539156525252005f * (2.0f * z2 - x2 - y2);
    Y[7]  = 1.0925484305920792f * x * zd;
    Y[8]  = 0.5462742152960396f * (x2 - y2);
    Y[9]  = 0.5900435899266435f * y * (3.0f * x2 - y2);
    Y[10] = 2.890611442640554f * x * y * zd;
    Y[11] = 0.4570457994644658f * y * (4.0f * z2 - x2 - y2);
    Y[12] = 0.3731763325901154f * zd * (2.0f * z2 - 3.0f * x2 - 3.0f * y2);
    Y[13] = 0.4570457994644658f * x * (4.0f * z2 - x2 - y2);
    Y[14] = 1.445305721320277f * zd * (x2 - y2);
    Y[15] = 0.5900435899266435f * x * (x2 - 3.0f * y2);
}

__global__ __launch_bounds__(256)
void fill_kernel(const float* __restrict__ dist,
                 const float* __restrict__ dirs,
                 const int* __restrict__ z,
                 const int* __restrict__ idx_i,
                 const int* __restrict__ idx_j,
                 int J)
{
    int e = blockIdx.x * blockDim.x + threadIdx.x;
    if (e >= J) return;
    float r  = __ldg(dist + e);
    float x  = __ldg(dirs + 3 * e + 0);
    float y  = __ldg(dirs + 3 * e + 1);
    float zd = __ldg(dirs + 3 * e + 2);
    int seg = __ldg(z + __ldg(idx_j + e)) + N_SPECIES * __ldg(idx_i + e);

    float lfc = __log2f(cutoff_branchless(r));
    float4 v  = make_float4(S_EXP * r, x, y, zd);

    int pos = atomicAdd(&d_cnt[seg], 1);
    if (pos < CAP) {
        Entry* ent = &d_bucket[seg * CAP + pos];
        ent->v   = v;          // 16B store
        ent->lfc = lfc;        // 4B store, same 32B sector
    } else {
        int op = atomicAdd(&d_cnt[NSEG], 1);
        if (op < OVF_CAP) {
            d_ovf[op].v = v; d_ovf[op].lfc = lfc; d_ovf_seg[op] = seg;
        }
    }
}

// R = 2^(lfc - t^2) for two consecutive n values; accumulate into acc0/acc1.
__device__ __forceinline__ void accum_edge(float sr, float x, float y, float zd,
                                           float lfc, const float cs[4][2],
                                           float* __restrict__ acc0,
                                           float* __restrict__ acc1)
{
    float Ra[4], Rb[4];
#pragma unroll
    for (int l = 0; l < 4; l++) {
        float ta = sr - cs[l][0];
        float tb = sr - cs[l][1];
        Ra[l] = ex2(fmaf(-ta, ta, lfc));
        Rb[l] = ex2(fmaf(-tb, tb, lfc));
    }

    float Y[LMMAX];
    sph_harm(x, y, zd, Y);

    const int LTAB[LMMAX] = {0,1,1,1,2,2,2,2,2,3,3,3,3,3,3,3};
#pragma unroll
    for (int lm = 0; lm < LMMAX; lm++) {
        int l = LTAB[lm];
        acc0[lm] += Ra[l] * Y[lm];
        acc1[lm] += Rb[l] * Y[lm];
    }
}

// One thread per (segment, n-pair): 32 register accumulators, plain v4 stores.
// Sequential slot order preserves bucket-read locality (R8 lesson).
__global__ __launch_bounds__(256)
void gather_kernel(const float* __restrict__ centers,
                   float* __restrict__ out)
{
    int tid = blockIdx.x * blockDim.x + threadIdx.x;
    if (tid >= NSEG * 4) return;
    int seg = tid >> 2;
    int np  = tid & 3;          // n0 = 2*np, n1 = 2*np+1

    float cs[4][2];
#pragma unroll
    for (int l = 0; l < 4; l++) {
        cs[l][0] = S_EXP * __ldg(centers + l * NMAX + 2 * np + 0);
        cs[l][1] = S_EXP * __ldg(centers + l * NMAX + 2 * np + 1);
    }

    float acc0[LMMAX], acc1[LMMAX];
#pragma unroll
    for (int i = 0; i < LMMAX; i++) { acc0[i] = 0.0f; acc1[i] = 0.0f; }

    int cnt_raw = d_cnt[seg];
    int cnt = cnt_raw > CAP ? CAP : cnt_raw;
    const Entry* bk = d_bucket + seg * CAP;

#pragma unroll 2
    for (int k = 0; k < cnt; k++) {
        float4 v  = bk[k].v;
        float lfc = bk[k].lfc;
        accum_edge(v.x, v.y, v.z, v.w, lfc, cs, acc0, acc1);
    }

    if (cnt_raw > CAP) {        // astronomically rare
        int novf = d_cnt[NSEG];
        if (novf > OVF_CAP) novf = OVF_CAP;
        for (int t = 0; t < novf; t++) {
            if (d_ovf_seg[t] == seg) {
                float4 v = d_ovf[t].v;
                accum_edge(v.x, v.y, v.z, v.w, d_ovf[t].lfc, cs, acc0, acc1);
            }
        }
    }

    float4* o = (float4*)(out + (size_t)seg * (NMAX * LMMAX) + np * 2 * LMMAX);
    o[0] = make_float4(acc0[0],  acc0[1],  acc0[2],  acc0[3]);
    o[1] = make_float4(acc0[4],  acc0[5],  acc0[6],  acc0[7]);
    o[2] = make_float4(acc0[8],  acc0[9],  acc0[10], acc0[11]);
    o[3] = make_float4(acc0[12], acc0[13], acc0[14], acc0[15]);
    o[4] = make_float4(acc1[0],  acc1[1],  acc1[2],  acc1[3]);
    o[5] = make_float4(acc1[4],  acc1[5],  acc1[6],  acc1[7]);
    o[6] = make_float4(acc1[8],  acc1[9],  acc1[10], acc1[11]);
    o[7] = make_float4(acc1[12], acc1[13], acc1[14], acc1[15]);
}

extern "C" void kernel_launch(void* const* d_in, const int* in_sizes, int n_in,
                              void* d_out, int out_size) {
    const float* dist    = (const float*)d_in[0];
    const float* dirs    = (const float*)d_in[1];
    const float* centers = (const float*)d_in[2];
    const int*   z       = (const int*)d_in[3];
    const int*   idx_i   = (const int*)d_in[4];
    const int*   idx_j   = (const int*)d_in[5];
    float*       out     = (float*)d_out;

    int J = in_sizes[0];

    void* cnt_ptr = nullptr;
    cudaGetSymbolAddress(&cnt_ptr, d_cnt);
    cudaMemsetAsync(cnt_ptr, 0, (NSEG + 1) * sizeof(int));

    fill_kernel<<<(J + 255) / 256, 256>>>(dist, dirs, z, idx_i, idx_j, J);
    gather_kernel<<<(NSEG * 4 + 255) / 256, 256>>>(centers, out);
}

// round 10
// speedup vs baseline: 1.0551x; 1.0551x over previous
#include <cuda_runtime.h>
#include <math.h>

#define NMAX 8
#define LMMAX 16
#define N_SPECIES 4
#define NSEG 80000
#define CAP 32
#define OVF_CAP 4096

static constexpr float RC = 5.0f;
static constexpr float SMOOTH_W = 0.5f;
static constexpr float PI_F = 3.14159265358979323846f;
static constexpr float S_EXP = 1.69864363f;   // sqrt(2*log2(e))

// Static scratch. d_cnt[NSEG] doubles as overflow counter.
// Split arrays (R8 lesson: keep footprint compact, ~51 MB total -> L2 resident).
__device__ int    d_cnt[NSEG + 1];
__device__ float4 d_bucket[NSEG * CAP];    // (S_EXP*r, x, y, z)   41 MB
__device__ float  d_blfc[NSEG * CAP];      // log2(fc)             10 MB
__device__ float4 d_ovf_data[OVF_CAP];
__device__ float  d_ovf_lfc[OVF_CAP];
__device__ int    d_ovf_seg[OVF_CAP];

__device__ __forceinline__ float ex2(float a) {
    float y;
    asm("ex2.approx.ftz.f32 %0, %1;" : "=f"(y) : "f"(a));
    return y;
}

__device__ __forceinline__ float cutoff_branchless(float r) {
    float t = __saturatef((r - (RC - SMOOTH_W)) * (1.0f / SMOOTH_W));
    return 0.5f * (1.0f + __cosf(PI_F * t));
}

__device__ __forceinline__ void sph_harm(float x, float y, float zd, float* Y) {
    float x2 = x * x, y2 = y * y, z2 = zd * zd;
    Y[0]  = 0.28209479177387814f;
    Y[1]  = 0.4886025119029199f * y;
    Y[2]  = 0.4886025119029199f * zd;
    Y[3]  = 0.4886025119029199f * x;
    Y[4]  = 1.0925484305920792f * x * y;
    Y[5]  = 1.0925484305920792f * y * zd;
    Y[6]  = 0.31539156525252005f * (2.0f * z2 - x2 - y2);
    Y[7]  = 1.0925484305920792f * x * zd;
    Y[8]  = 0.5462742152960396f * (x2 - y2);
    Y[9]  = 0.5900435899266435f * y * (3.0f * x2 - y2);
    Y[10] = 2.890611442640554f * x * y * zd;
    Y[11] = 0.4570457994644658f * y * (4.0f * z2 - x2 - y2);
    Y[12] = 0.3731763325901154f * zd * (2.0f * z2 - 3.0f * x2 - 3.0f * y2);
    Y[13] = 0.4570457994644658f * x * (4.0f * z2 - x2 - y2);
    Y[14] = 1.445305721320277f * zd * (x2 - y2);
    Y[15] = 0.5900435899266435f * x * (x2 - 3.0f * y2);
}

__global__ __launch_bounds__(256)
void fill_kernel(const float* __restrict__ dist,
                 const float* __restrict__ dirs,
                 const int* __restrict__ z,
                 const int* __restrict__ idx_i,
                 const int* __restrict__ idx_j,
                 int J)
{
    int e = blockIdx.x * blockDim.x + threadIdx.x;
    if (e >= J) return;
    float r  = __ldg(dist + e);
    float x  = __ldg(dirs + 3 * e + 0);
    float y  = __ldg(dirs + 3 * e + 1);
    float zd = __ldg(dirs + 3 * e + 2);
    int seg = __ldg(z + __ldg(idx_j + e)) + N_SPECIES * __ldg(idx_i + e);

    // 90% of edges have r <= rc - w -> fc = 1 -> lfc = 0 (skip cos/log2)
    float lfc = (r <= RC - SMOOTH_W) ? 0.0f : __log2f(cutoff_branchless(r));
    float4 v  = make_float4(S_EXP * r, x, y, zd);

    int pos = atomicAdd(&d_cnt[seg], 1);
    if (pos < CAP) {
        d_bucket[seg * CAP + pos] = v;
        d_blfc[seg * CAP + pos]   = lfc;
    } else {
        int op = atomicAdd(&d_cnt[NSEG], 1);
        if (op < OVF_CAP) {
            d_ovf_data[op] = v; d_ovf_lfc[op] = lfc; d_ovf_seg[op] = seg;
        }
    }
}

// R = 2^(lfc - t^2) for two consecutive n values; accumulate into acc0/acc1.
__device__ __forceinline__ void accum_edge(float sr, float x, float y, float zd,
                                           float lfc, const float cs[4][2],
                                           float* __restrict__ acc0,
                                           float* __restrict__ acc1)
{
    float Ra[4], Rb[4];
#pragma unroll
    for (int l = 0; l < 4; l++) {
        float ta = sr - cs[l][0];
        float tb = sr - cs[l][1];
        Ra[l] = ex2(fmaf(-ta, ta, lfc));
        Rb[l] = ex2(fmaf(-tb, tb, lfc));
    }

    float Y[LMMAX];
    sph_harm(x, y, zd, Y);

    const int LTAB[LMMAX] = {0,1,1,1,2,2,2,2,2,3,3,3,3,3,3,3};
#pragma unroll
    for (int lm = 0; lm < LMMAX; lm++) {
        int l = LTAB[lm];
        acc0[lm] += Ra[l] * Y[lm];
        acc1[lm] += Rb[l] * Y[lm];
    }
}

// One thread per (segment, n-pair), direct sequential indexing (R6 locality).
__global__ __launch_bounds__(256)
void gather_kernel(const float* __restrict__ centers,
                   float* __restrict__ out)
{
    int tid = blockIdx.x * blockDim.x + threadIdx.x;
    if (tid >= NSEG * 4) return;
    int seg = tid >> 2;
    int np  = tid & 3;          // n0 = 2*np, n1 = 2*np+1

    float cs[4][2];
#pragma unroll
    for (int l = 0; l < 4; l++) {
        cs[l][0] = S_EXP * __ldg(centers + l * NMAX + 2 * np + 0);
        cs[l][1] = S_EXP * __ldg(centers + l * NMAX + 2 * np + 1);
    }

    float acc0[LMMAX], acc1[LMMAX];
#pragma unroll
    for (int i = 0; i < LMMAX; i++) { acc0[i] = 0.0f; acc1[i] = 0.0f; }

    int cnt_raw = d_cnt[seg];
    int cnt = cnt_raw > CAP ? CAP : cnt_raw;
    const float4* bk = d_bucket + seg * CAP;
    const float*  bf = d_blfc   + seg * CAP;

#pragma unroll 2
    for (int k = 0; k < cnt; k++) {
        float4 v  = bk[k];
        float lfc = bf[k];
        accum_edge(v.x, v.y, v.z, v.w, lfc, cs, acc0, acc1);
    }

    if (cnt_raw > CAP) {        // astronomically rare
        int novf = d_cnt[NSEG];
        if (novf > OVF_CAP) novf = OVF_CAP;
        for (int t = 0; t < novf; t++) {
            if (d_ovf_seg[t] == seg) {
                float4 v = d_ovf_data[t];
                accum_edge(v.x, v.y, v.z, v.w, d_ovf_lfc[t], cs, acc0, acc1);
            }
        }
    }

    float4* o = (float4*)(out + (size_t)seg * (NMAX * LMMAX) + np * 2 * LMMAX);
    o[0] = make_float4(acc0[0],  acc0[1],  acc0[2],  acc0[3]);
    o[1] = make_float4(acc0[4],  acc0[5],  acc0[6],  acc0[7]);
    o[2] = make_float4(acc0[8],  acc0[9],  acc0[10], acc0[11]);
    o[3] = make_float4(acc0[12], acc0[13], acc0[14], acc0[15]);
    o[4] = make_float4(acc1[0],  acc1[1],  acc1[2],  acc1[3]);
    o[5] = make_float4(acc1[4],  acc1[5],  acc1[6],  acc1[7]);
    o[6] = make_float4(acc1[8],  acc1[9],  acc1[10], acc1[11]);
    o[7] = make_float4(acc1[12], acc1[13], acc1[14], acc1[15]);
}

extern "C" void kernel_launch(void* const* d_in, const int* in_sizes, int n_in,
                              void* d_out, int out_size) {
    const float* dist    = (const float*)d_in[0];
    const float* dirs    = (const float*)d_in[1];
    const float* centers = (const float*)d_in[2];
    const int*   z       = (const int*)d_in[3];
    const int*   idx_i   = (const int*)d_in[4];
    const int*   idx_j   = (const int*)d_in[5];
    float*       out     = (float*)d_out;

    int J = in_sizes[0];

    void* cnt_ptr = nullptr;
    cudaGetSymbolAddress(&cnt_ptr, d_cnt);
    cudaMemsetAsync(cnt_ptr, 0, (NSEG + 1) * sizeof(int));

    fill_kernel<<<(J + 255) / 256, 256>>>(dist, dirs, z, idx_i, idx_j, J);
    gather_kernel<<<(NSEG * 4 + 255) / 256, 256>>>(centers, out);
}

// round 11
// speedup vs baseline: 1.2187x; 1.1550x over previous
#include <cuda_runtime.h>
#include <math.h>

#define NMAX 8
#define LMMAX 16
#define N_SPECIES 4
#define NSEG 80000
#define CAP 32
#define OVF_CAP 4096

static constexpr float RC = 5.0f;
static constexpr float SMOOTH_W = 0.5f;
static constexpr float PI_F = 3.14159265358979323846f;
static constexpr float S_EXP = 1.69864363f;   // sqrt(2*log2(e))

// Static scratch, R6 layout exactly: one float4 stream, nothing else hot.
__device__ int    d_cnt[NSEG + 1];          // [NSEG] = overflow counter
__device__ float4 d_bucket[NSEG * CAP];     // (r, x, y, z)
__device__ float4 d_ovf_data[OVF_CAP];
__device__ int    d_ovf_seg[OVF_CAP];

__device__ __forceinline__ float ex2(float a) {
    float y;
    asm("ex2.approx.ftz.f32 %0, %1;" : "=f"(y) : "f"(a));
    return y;
}

__device__ __forceinline__ float lg2(float a) {
    float y;
    asm("lg2.approx.ftz.f32 %0, %1;" : "=f"(y) : "f"(a));
    return y;
}

// log2(cutoff(r)), branchless: 0 for r<=4.5, -inf for r>=5 (ex2 -> 0, exact).
__device__ __forceinline__ float log2_cutoff(float r) {
    float t = __saturatef((r - (RC - SMOOTH_W)) * (1.0f / SMOOTH_W));
    return lg2(0.5f * (1.0f + __cosf(PI_F * t)));
}

__device__ __forceinline__ void sph_harm(float x, float y, float zd, float* Y) {
    float x2 = x * x, y2 = y * y, z2 = zd * zd;
    Y[0]  = 0.28209479177387814f;
    Y[1]  = 0.4886025119029199f * y;
    Y[2]  = 0.4886025119029199f * zd;
    Y[3]  = 0.4886025119029199f * x;
    Y[4]  = 1.0925484305920792f * x * y;
    Y[5]  = 1.0925484305920792f * y * zd;
    Y[6]  = 0.31539156525252005f * (2.0f * z2 - x2 - y2);
    Y[7]  = 1.0925484305920792f * x * zd;
    Y[8]  = 0.5462742152960396f * (x2 - y2);
    Y[9]  = 0.5900435899266435f * y * (3.0f * x2 - y2);
    Y[10] = 2.890611442640554f * x * y * zd;
    Y[11] = 0.4570457994644658f * y * (4.0f * z2 - x2 - y2);
    Y[12] = 0.3731763325901154f * zd * (2.0f * z2 - 3.0f * x2 - 3.0f * y2);
    Y[13] = 0.4570457994644658f * x * (4.0f * z2 - x2 - y2);
    Y[14] = 1.445305721320277f * zd * (x2 - y2);
    Y[15] = 0.5900435899266435f * x * (x2 - 3.0f * y2);
}

__global__ __launch_bounds__(256)
void fill_kernel(const float* __restrict__ dist,
                 const float* __restrict__ dirs,
                 const int* __restrict__ z,
                 const int* __restrict__ idx_i,
                 const int* __restrict__ idx_j,
                 int J)
{
    int e = blockIdx.x * blockDim.x + threadIdx.x;
    if (e >= J) return;
    float r  = __ldg(dist + e);
    float x  = __ldg(dirs + 3 * e + 0);
    float y  = __ldg(dirs + 3 * e + 1);
    float zd = __ldg(dirs + 3 * e + 2);
    int seg = __ldg(z + __ldg(idx_j + e)) + N_SPECIES * __ldg(idx_i + e);

    float4 v = make_float4(r, x, y, zd);
    int pos = atomicAdd(&d_cnt[seg], 1);
    if (pos < CAP) {
        d_bucket[seg * CAP + pos] = v;
    } else {
        int op = atomicAdd(&d_cnt[NSEG], 1);
        if (op < OVF_CAP) { d_ovf_data[op] = v; d_ovf_seg[op] = seg; }
    }
}

// One edge, two consecutive n values. R = 2^(lfc - t^2), lfc computed in-gather.
__device__ __forceinline__ void accum_edge(float r, float x, float y, float zd,
                                           const float cs[4][2],
                                           float* __restrict__ acc0,
                                           float* __restrict__ acc1)
{
    float lfc = log2_cutoff(r);

    float Ra[4], Rb[4];
#pragma unroll
    for (int l = 0; l < 4; l++) {
        float ta = fmaf(r, S_EXP, -cs[l][0]);
        float tb = fmaf(r, S_EXP, -cs[l][1]);
        Ra[l] = ex2(fmaf(-ta, ta, lfc));
        Rb[l] = ex2(fmaf(-tb, tb, lfc));
    }

    float Y[LMMAX];
    sph_harm(x, y, zd, Y);

    const int LTAB[LMMAX] = {0,1,1,1,2,2,2,2,2,3,3,3,3,3,3,3};
#pragma unroll
    for (int lm = 0; lm < LMMAX; lm++) {
        int l = LTAB[lm];
        acc0[lm] += Ra[l] * Y[lm];
        acc1[lm] += Rb[l] * Y[lm];
    }
}

// One thread per (segment, n-pair); direct sequential indexing (R6 locality).
__global__ __launch_bounds__(128)
void gather_kernel(const float* __restrict__ centers,
                   float* __restrict__ out)
{
    int tid = blockIdx.x * blockDim.x + threadIdx.x;
    if (tid >= NSEG * 4) return;
    int seg = tid >> 2;
    int np  = tid & 3;          // n0 = 2*np, n1 = 2*np+1

    float cs[4][2];             // S_EXP * center
#pragma unroll
    for (int l = 0; l < 4; l++) {
        cs[l][0] = S_EXP * __ldg(centers + l * NMAX + 2 * np + 0);
        cs[l][1] = S_EXP * __ldg(centers + l * NMAX + 2 * np + 1);
    }

    float acc0[LMMAX], acc1[LMMAX];
#pragma unroll
    for (int i = 0; i < LMMAX; i++) { acc0[i] = 0.0f; acc1[i] = 0.0f; }

    int cnt_raw = d_cnt[seg];
    int cnt = cnt_raw > CAP ? CAP : cnt_raw;
    const float4* bk = d_bucket + seg * CAP;

#pragma unroll 4
    for (int k = 0; k < cnt; k++) {
        float4 v = bk[k];
        accum_edge(v.x, v.y, v.z, v.w, cs, acc0, acc1);
    }

    if (cnt_raw > CAP) {        // astronomically rare
        int novf = d_cnt[NSEG];
        if (novf > OVF_CAP) novf = OVF_CAP;
        for (int t = 0; t < novf; t++) {
            if (d_ovf_seg[t] == seg) {
                float4 v = d_ovf_data[t];
                accum_edge(v.x, v.y, v.z, v.w, cs, acc0, acc1);
            }
        }
    }

    float4* o = (float4*)(out + (size_t)seg * (NMAX * LMMAX) + np * 2 * LMMAX);
    o[0] = make_float4(acc0[0],  acc0[1],  acc0[2],  acc0[3]);
    o[1] = make_float4(acc0[4],  acc0[5],  acc0[6],  acc0[7]);
    o[2] = make_float4(acc0[8],  acc0[9],  acc0[10], acc0[11]);
    o[3] = make_float4(acc0[12], acc0[13], acc0[14], acc0[15]);
    o[4] = make_float4(acc1[0],  acc1[1],  acc1[2],  acc1[3]);
    o[5] = make_float4(acc1[4],  acc1[5],  acc1[6],  acc1[7]);
    o[6] = make_float4(acc1[8],  acc1[9],  acc1[10], acc1[11]);
    o[7] = make_float4(acc1[12], acc1[13], acc1[14], acc1[15]);
}

extern "C" void kernel_launch(void* const* d_in, const int* in_sizes, int n_in,
                              void* d_out, int out_size) {
    const float* dist    = (const float*)d_in[0];
    const float* dirs    = (const float*)d_in[1];
    const float* centers = (const float*)d_in[2];
    const int*   z       = (const int*)d_in[3];
    const int*   idx_i   = (const int*)d_in[4];
    const int*   idx_j   = (const int*)d_in[5];
    float*       out     = (float*)d_out;

    int J = in_sizes[0];

    void* cnt_ptr = nullptr;
    cudaGetSymbolAddress(&cnt_ptr, d_cnt);
    cudaMemsetAsync(cnt_ptr, 0, (NSEG + 1) * sizeof(int));

    fill_kernel<<<(J + 255) / 256, 256>>>(dist, dirs, z, idx_i, idx_j, J);
    gather_kernel<<<(NSEG * 4 + 127) / 128, 128>>>(centers, out);
}

// round 14
// speedup vs baseline: 1.2263x; 1.0062x over previous
#include <cuda_runtime.h>
#include <math.h>

#define NMAX 8
#define LMMAX 16
#define N_SPECIES 4
#define NSEG 80000
#define CAP 32
#define OVF_CAP 4096
#define SEGS_PER_BLOCK 32

static constexpr float RC = 5.0f;
static constexpr float SMOOTH_W = 0.5f;
static constexpr float PI_F = 3.14159265358979323846f;
static constexpr float S_EXP = 1.69864363f;   // sqrt(2*log2(e))

// Static scratch, R6/R11 layout: one float4 stream.
__device__ int    d_cnt[NSEG + 1];          // [NSEG] = overflow counter
__device__ int    d_done;                   // last-block ticket
__device__ float4 d_bucket[NSEG * CAP];     // (r, x, y, z)
__device__ float4 d_ovf_data[OVF_CAP];
__device__ int    d_ovf_seg[OVF_CAP];

__device__ __forceinline__ float ex2(float a) {
    float y;
    asm("ex2.approx.ftz.f32 %0, %1;" : "=f"(y) : "f"(a));
    return y;
}

__device__ __forceinline__ float lg2(float a) {
    float y;
    asm("lg2.approx.ftz.f32 %0, %1;" : "=f"(y) : "f"(a));
    return y;
}

// log2(cutoff(r)), branchless: 0 for r<=4.5, -inf for r>=5 (ex2 -> 0, exact).
__device__ __forceinline__ float log2_cutoff(float r) {
    float t = __saturatef((r - (RC - SMOOTH_W)) * (1.0f / SMOOTH_W));
    return lg2(0.5f * (1.0f + __cosf(PI_F * t)));
}

__device__ __forceinline__ void sph_harm(float x, float y, float zd, float* Y) {
    float x2 = x * x, y2 = y * y, z2 = zd * zd;
    Y[0]  = 0.28209479177387814f;
    Y[1]  = 0.4886025119029199f * y;
    Y[2]  = 0.4886025119029199f * zd;
    Y[3]  = 0.4886025119029199f * x;
    Y[4]  = 1.0925484305920792f * x * y;
    Y[5]  = 1.0925484305920792f * y * zd;
    Y[6]  = 0.31539156525252005f * (2.0f * z2 - x2 - y2);
    Y[7]  = 1.0925484305920792f * x * zd;
    Y[8]  = 0.5462742152960396f * (x2 - y2);
    Y[9]  = 0.5900435899266435f * y * (3.0f * x2 - y2);
    Y[10] = 2.890611442640554f * x * y * zd;
    Y[11] = 0.4570457994644658f * y * (4.0f * z2 - x2 - y2);
    Y[12] = 0.3731763325901154f * zd * (2.0f * z2 - 3.0f * x2 - 3.0f * y2);
    Y[13] = 0.4570457994644658f * x * (4.0f * z2 - x2 - y2);
    Y[14] = 1.445305721320277f * zd * (x2 - y2);
    Y[15] = 0.5900435899266435f * x * (x2 - 3.0f * y2);
}

__global__ __launch_bounds__(256)
void fill_kernel(const float* __restrict__ dist,
                 const float* __restrict__ dirs,
                 const int* __restrict__ z,
                 const int* __restrict__ idx_i,
                 const int* __restrict__ idx_j,
                 int J)
{
    int e = blockIdx.x * blockDim.x + threadIdx.x;
    if (e >= J) return;
    float r  = __ldg(dist + e);
    float x  = __ldg(dirs + 3 * e + 0);
    float y  = __ldg(dirs + 3 * e + 1);
    float zd = __ldg(dirs + 3 * e + 2);
    int seg = __ldg(z + __ldg(idx_j + e)) + N_SPECIES * __ldg(idx_i + e);

    float4 v = make_float4(r, x, y, zd);
    int pos = atomicAdd(&d_cnt[seg], 1);
    if (pos < CAP) {
        d_bucket[seg * CAP + pos] = v;
    } else {
        int op = atomicAdd(&d_cnt[NSEG], 1);
        if (op < OVF_CAP) { d_ovf_data[op] = v; d_ovf_seg[op] = seg; }
    }
}

// One edge, two consecutive n values. R = 2^(lfc - t^2).
__device__ __forceinline__ void accum_edge(float r, float x, float y, float zd,
                                           const float cs[4][2],
                                           float* __restrict__ acc0,
                                           float* __restrict__ acc1)
{
    float lfc = log2_cutoff(r);

    float Ra[4], Rb[4];
#pragma unroll
    for (int l = 0; l < 4; l++) {
        float ta = fmaf(r, S_EXP, -cs[l][0]);
        float tb = fmaf(r, S_EXP, -cs[l][1]);
        Ra[l] = ex2(fmaf(-ta, ta, lfc));
        Rb[l] = ex2(fmaf(-tb, tb, lfc));
    }

    float Y[LMMAX];
    sph_harm(x, y, zd, Y);

    const int LTAB[LMMAX] = {0,1,1,1,2,2,2,2,2,3,3,3,3,3,3,3};
#pragma unroll
    for (int lm = 0; lm < LMMAX; lm++) {
        int l = LTAB[lm];
        acc0[lm] += Ra[l] * Y[lm];
        acc1[lm] += Rb[l] * Y[lm];
    }
}

// Block owns 32 consecutive segments; rank-sorts their counts so each warp's 8
// segments have near-equal counts (block-local version of the R7 idea, zero
// global overhead). Self-cleans d_cnt; last block clears the overflow counter.
__global__ __launch_bounds__(128)
void gather_kernel(const float* __restrict__ centers,
                   float* __restrict__ out)
{
    __shared__ int s_rawcnt[SEGS_PER_BLOCK];
    __shared__ int s_seg[SEGS_PER_BLOCK];
    __shared__ int s_cnt[SEGS_PER_BLOCK];

    int t = threadIdx.x;
    int base_seg = blockIdx.x * SEGS_PER_BLOCK;   // grid = 2500, exact cover

    if (t < SEGS_PER_BLOCK)
        s_rawcnt[t] = d_cnt[base_seg + t];
    __syncthreads();

    if (t < SEGS_PER_BLOCK) {
        int c = s_rawcnt[t];
        int rank = 0;
#pragma unroll
        for (int j = 0; j < SEGS_PER_BLOCK; j++) {
            int cj = s_rawcnt[j];
            rank += (cj > c) || (cj == c && j < t);   // descending, stable
        }
        s_seg[rank] = base_seg + t;
        s_cnt[rank] = c;
    }
    __syncthreads();

    int slot = t >> 2;
    int np   = t & 3;                 // n0 = 2*np, n1 = 2*np+1
    int seg      = s_seg[slot];
    int cnt_raw  = s_cnt[slot];

    float cs[4][2];                   // S_EXP * center
#pragma unroll
    for (int l = 0; l < 4; l++) {
        cs[l][0] = S_EXP * __ldg(centers + l * NMAX + 2 * np + 0);
        cs[l][1] = S_EXP * __ldg(centers + l * NMAX + 2 * np + 1);
    }

    float acc0[LMMAX], acc1[LMMAX];
#pragma unroll
    for (int i = 0; i < LMMAX; i++) { acc0[i] = 0.0f; acc1[i] = 0.0f; }

    int cnt = cnt_raw > CAP ? CAP : cnt_raw;
    const float4* bk = d_bucket + seg * CAP;

#pragma unroll 4
    for (int k = 0; k < cnt; k++) {
        float4 v = bk[k];
        accum_edge(v.x, v.y, v.z, v.w, cs, acc0, acc1);
    }

    if (cnt_raw > CAP) {              // astronomically rare
        int novf = d_cnt[NSEG];
        if (novf > OVF_CAP) novf = OVF_CAP;
        for (int k2 = 0; k2 < novf; k2++) {
            if (d_ovf_seg[k2] == seg) {
                float4 v = d_ovf_data[k2];
                accum_edge(v.x, v.y, v.z, v.w, cs, acc0, acc1);
            }
        }
    }

    float4* o = (float4*)(out + (size_t)seg * (NMAX * LMMAX) + np * 2 * LMMAX);
    o[0] = make_float4(acc0[0],  acc0[1],  acc0[2],  acc0[3]);
    o[1] = make_float4(acc0[4],  acc0[5],  acc0[6],  acc0[7]);
    o[2] = make_float4(acc0[8],  acc0[9],  acc0[10], acc0[11]);
    o[3] = make_float4(acc0[12], acc0[13], acc0[14], acc0[15]);
    o[4] = make_float4(acc1[0],  acc1[1],  acc1[2],  acc1[3]);
    o[5] = make_float4(acc1[4],  acc1[5],  acc1[6],  acc1[7]);
    o[6] = make_float4(acc1[8],  acc1[9],  acc1[10], acc1[11]);
    o[7] = make_float4(acc1[12], acc1[13], acc1[14], acc1[15]);

    // Self-clean for next run: counts read only via smem above, so this is safe.
    if (np == 0) d_cnt[seg] = 0;

    __syncthreads();
    if (t == 0) {
        __threadfence();
        int ticket = atomicAdd(&d_done, 1);
        if (ticket == (int)gridDim.x - 1) {
            d_cnt[NSEG] = 0;          // overflow counter
            d_done = 0;
        }
    }
}

extern "C" void kernel_launch(void* const* d_in, const int* in_sizes, int n_in,
                              void* d_out, int out_size) {
    const float* dist    = (const float*)d_in[0];
    const float* dirs    = (const float*)d_in[1];
    const float* centers = (const float*)d_in[2];
    const int*   z       = (const int*)d_in[3];
    const int*   idx_i   = (const int*)d_in[4];
    const int*   idx_j   = (const int*)d_in[5];
    float*       out     = (float*)d_out;

    int J = in_sizes[0];

    fill_kernel<<<(J + 255) / 256, 256>>>(dist, dirs, z, idx_i, idx_j, J);
    gather_kernel<<<NSEG / SEGS_PER_BLOCK, 128>>>(centers, out);
}